// round 15
// baseline (speedup 1.0000x reference)
#include <cuda_runtime.h>
#include <cuda_fp16.h>

// SSIM loss, single fused kernel, fp16 datapath with CENTERED fields.
// u' = p+t-1, v = p-t. Conv fields X=(u',v), Y=(u'^2,v^2) as half2.
// Weights sum to 1: A=A'+1, C=C'+2A'+1, recovered exactly in fp32 epilogue.
// R15: halo-load + h-pass fused into warp-owned 4-row batches:
//   warp loads its rows -> __syncwarp -> h-convs the SAME rows.
// Removes one block barrier and overlaps LDG drain with conv across warps.
// Conv inner loops / v-pass / epilogue byte-identical to R14 (128.9us).

#define TW    32
#define TH    128
#define HALO  5
#define EW    42
#define EH    138
#define XP    44              // pitch (half2), EVEN -> 8B-aligned pair loads
#define HP    33              // pitch (8B rec) h-pass array
#define NBATCH 35             // ceil(EH/4)

#define IMG_H 512
#define IMG_W 512
#define N_PLANES 96
#define GX    16
#define GY    4
#define NBLK  (GX*GY*N_PLANES)   // 6144
#define N_PIX 25165824.0

#define SX_OFF   0
#define HQ_OFF   (EH*XP*4)             // 24288
#define RED_OFF  (HQ_OFF + EH*HP*8)    // 60720
#define SMEM_TOTAL (RED_OFF + 16*4 + 16)   // ~59.4KB -> 3 blocks/SM

typedef unsigned long long ull;

__device__ constexpr float GW[11] = {
    0.00102838f, 0.00759877f, 0.03600077f, 0.10936071f, 0.21300553f,
    0.26601175f,
    0.21300553f, 0.10936071f, 0.03600077f, 0.00759877f, 0.00102838f
};

struct __align__(8) HQrec { __half2 ab; __half2 cd; };

__device__ float g_part[NBLK];
__device__ unsigned int g_count;

__global__ __launch_bounds__(512, 3)
void ssim_tile_kernel(const float* __restrict__ pred,
                      const float* __restrict__ targ,
                      float* __restrict__ out)
{
    extern __shared__ char smem[];
    __half2 (*sX)[XP] = (__half2(*)[XP])(smem + SX_OFF);
    HQrec   (*hQ)[HP] = (HQrec(*)[HP])(smem + HQ_OFF);
    float* red    = (float*)(smem + RED_OFF);
    int* lastflag = (int*)(smem + RED_OFF + 16*4);

    const int tid  = threadIdx.x;
    const int wid  = tid >> 5;
    const int lane = tid & 31;
    const int ty0 = blockIdx.y * TH;
    const int tx0 = blockIdx.x * TW;
    const size_t pbase = (size_t)blockIdx.z * (IMG_H * IMG_W);

    const bool interior = (blockIdx.x != 0) & (blockIdx.x != GX - 1) &
                          (blockIdx.y != 0) & (blockIdx.y != GY - 1);

    // ---- fused halo-load + h-pass: warp-owned batches of 4 rows ----
    for (int b = wid; b < NBATCH; b += 16) {
        const int r0 = b * 4;

        // load rows r0..r0+3 (lane-contiguous, 2 col-steps of 32)
        #pragma unroll
        for (int rr = 0; rr < 4; rr++) {
            int r = r0 + rr;
            if (r < EH) {
                int gy = ty0 + r - HALO;
                #pragma unroll
                for (int s = 0; s < 2; s++) {
                    int c = lane + s * 32;
                    if (s == 0 || c < EW) {
                        int gx = tx0 + c - HALO;
                        float a = 0.f, bb = 0.f;
                        if (interior) {
                            size_t off = pbase + (size_t)gy * IMG_W + gx;
                            a  = pred[off];
                            bb = targ[off];
                        } else {
                            bool ok = ((unsigned)gy < (unsigned)IMG_H) &
                                      ((unsigned)gx < (unsigned)IMG_W);
                            if (ok) {
                                size_t off = pbase + (size_t)gy * IMG_W + gx;
                                a  = pred[off];
                                bb = targ[off];
                            }
                        }
                        if (c < EW)
                            sX[r][c] = __floats2half2_rn(a + bb - 1.0f, a - bb);
                    }
                }
            }
        }
        __syncwarp();

        // h-conv of the same 4 rows: lane -> (row r0+(lane>>3), item lane&7)
        {
            const int r  = r0 + (lane >> 3);
            if (r < EH) {
                const int c0 = (lane & 7) * 4;
                __half2 aX[4], aY[4];
                #pragma unroll
                for (int j = 0; j < 4; j++) {
                    aX[j] = __floats2half2_rn(0.f, 0.f);
                    aY[j] = aX[j];
                }

                // 14 taps as 7 aligned 8B pair-loads (r*XP + c0 even)
                const ull* rowp = (const ull*)(&sX[r][c0]);
                #pragma unroll
                for (int ip = 0; ip < 7; ip++) {
                    ull pr = rowp[ip];
                    __half2 X0 = ((const __half2*)&pr)[0];
                    __half2 X1 = ((const __half2*)&pr)[1];
                    __half2 Y0 = __hmul2(X0, X0);
                    __half2 Y1 = __hmul2(X1, X1);
                    #pragma unroll
                    for (int j = 0; j < 4; j++) {
                        int k0 = 2 * ip - j;
                        if (k0 >= 0 && k0 <= 10) {
                            __half2 w2 = __float2half2_rn(GW[k0]);
                            aX[j] = __hfma2(X0, w2, aX[j]);
                            aY[j] = __hfma2(Y0, w2, aY[j]);
                        }
                        int k1 = 2 * ip + 1 - j;
                        if (k1 >= 0 && k1 <= 10) {
                            __half2 w2 = __float2half2_rn(GW[k1]);
                            aX[j] = __hfma2(X1, w2, aX[j]);
                            aY[j] = __hfma2(Y1, w2, aY[j]);
                        }
                    }
                }
                #pragma unroll
                for (int j = 0; j < 4; j++) {
                    HQrec q; q.ab = aX[j]; q.cd = aY[j];
                    hQ[r][c0 + j] = q;      // one STS.64
                }
            }
        }
    }
    __syncthreads();

    // ---- vertical pass + SSIM: thread -> (x, 8 rows as 2 rounds of 4) ----
    const int x   = tid & 31;
    const int yb  = (tid >> 5) * 8;    // 0..120

    float lsum = 0.f;
    const float C1 = 1e-4f;
    const float C2 = 9e-4f;

    #pragma unroll 1
    for (int rd = 0; rd < 2; rd++) {
        const int y0 = yb + rd * 4;

        __half2 vX[4], vY[4];
        #pragma unroll
        for (int j = 0; j < 4; j++) {
            vX[j] = __floats2half2_rn(0.f, 0.f);
            vY[j] = vX[j];
        }

        #pragma unroll
        for (int i = 0; i < 14; i++) {
            HQrec q = hQ[y0 + i][x];   // one LDS.64 per tap
            #pragma unroll
            for (int j = 0; j < 4; j++) {
                int k = i - j;
                if (k >= 0 && k <= 10) {
                    __half2 w2 = __float2half2_rn(GW[k]);
                    vX[j] = __hfma2(q.ab, w2, vX[j]);
                    vY[j] = __hfma2(q.cd, w2, vY[j]);
                }
            }
        }

        #pragma unroll
        for (int j = 0; j < 4; j++) {
            float Ap = __low2float(vX[j]);    // A' = A - 1
            float B  = __high2float(vX[j]);
            float Cp = __low2float(vY[j]);    // C' = C - 2A' - 1
            float Dv = __high2float(vY[j]);
            float A2 = fmaf(Ap, Ap + 2.0f, 1.0f);   // A^2
            float B2 = B * B;
            float t2m12 = (A2 - B2) * 0.5f;
            float msum  = (A2 + B2) * 0.5f;
            float e = Ap + 0.5f;                    // (C-D)/2 recovery term
            float t2s12 = (Cp - Dv) * 0.5f + e - t2m12;
            float ssum  = (Cp + Dv) * 0.5f + e - msum;
            float num = (t2m12 + C1) * (t2s12 + C2);
            float den = (msum + C1) * (ssum + C2) + 1e-8f;
            lsum += __fdividef(num, den);
        }
    }

    // ---- block reduce, unique partial slot ----
    #pragma unroll
    for (int o = 16; o; o >>= 1)
        lsum += __shfl_xor_sync(0xffffffffu, lsum, o);
    if (lane == 0) red[wid] = lsum;
    __syncthreads();

    if (tid == 0) {
        float s = 0.f;
        #pragma unroll
        for (int w = 0; w < 16; w++) s += red[w];
        int bid = (blockIdx.z * GY + blockIdx.y) * GX + blockIdx.x;
        g_part[bid] = s;
        __threadfence();
        unsigned int prev = atomicAdd(&g_count, 1u);
        *lastflag = (prev == NBLK - 1) ? 1 : 0;
    }
    __syncthreads();

    // ---- last block: final reduction over all partials ----
    if (*lastflag) {
        __threadfence();
        const float4* p4 = (const float4*)g_part;
        float s = 0.f;
        #pragma unroll
        for (int it = 0; it < 3; it++) {
            float4 v = p4[tid + it * 512];
            s += (v.x + v.y) + (v.z + v.w);
        }
        #pragma unroll
        for (int o = 16; o; o >>= 1)
            s += __shfl_xor_sync(0xffffffffu, s, o);
        if (lane == 0) red[wid] = s;
        __syncthreads();
        if (tid == 0) {
            float t = 0.f;
            #pragma unroll
            for (int w = 0; w < 16; w++) t += red[w];
            out[0] = (float)(1.0 - (double)t * (1.0 / N_PIX));
            g_count = 0;   // self-reset for next graph replay
        }
    }
}

extern "C" void kernel_launch(void* const* d_in, const int* in_sizes, int n_in,
                              void* d_out, int out_size)
{
    const float* pred = (const float*)d_in[0];
    const float* targ = (const float*)d_in[1];

    cudaFuncSetAttribute(ssim_tile_kernel,
                         cudaFuncAttributeMaxDynamicSharedMemorySize, SMEM_TOTAL);
    dim3 grid(GX, GY, N_PLANES);   // 16 x 4 x 96
    ssim_tile_kernel<<<grid, 512, SMEM_TOTAL>>>(pred, targ, (float*)d_out);
}

// round 16
// speedup vs baseline: 1.5329x; 1.5329x over previous
#include <cuda_runtime.h>
#include <cuda_fp16.h>

// SSIM loss, single fused kernel, fp16 datapath with CENTERED fields.
// u' = p+t-1, v = p-t. Conv fields X=(u',v), Y=(u'^2,v^2) as half2.
// Weights sum to 1: A=A'+1, C=C'+2A'+1, recovered exactly in fp32 epilogue.
// R16 = R14 (128.9us) with layout-only fixes:
//  - XP=42: h-pass pair-load row stride 168B -> 2-way banked (was 4-way at
//    XP=44), halving h-pass LDS phases; halo store becomes fully contiguous
//  - HP=34 (even): hQ stores emitted as 2x STS.128 instead of 4x STS.64
// Phase order, load batching, arithmetic all byte-identical to R14.

#define TW    32
#define TH    128
#define HALO  5
#define EW    42
#define EH    138
#define XP    42              // pitch (half2): stride 168B -> 2-way conflicts
#define HP    34              // pitch (8B rec), EVEN -> 16B-aligned pair STS

#define IMG_H 512
#define IMG_W 512
#define N_PLANES 96
#define GX    16
#define GY    4
#define NBLK  (GX*GY*N_PLANES)   // 6144
#define N_PIX 25165824.0

#define SX_OFF   0
#define HQ_OFF   (EH*XP*4)             // 23184
#define RED_OFF  (HQ_OFF + EH*HP*8)    // 60720
#define SMEM_TOTAL (RED_OFF + 16*4 + 16)   // ~59.4KB -> 3 blocks/SM

typedef unsigned long long ull;

__device__ constexpr float GW[11] = {
    0.00102838f, 0.00759877f, 0.03600077f, 0.10936071f, 0.21300553f,
    0.26601175f,
    0.21300553f, 0.10936071f, 0.03600077f, 0.00759877f, 0.00102838f
};

struct __align__(8) HQrec { __half2 ab; __half2 cd; };

__device__ float g_part[NBLK];
__device__ unsigned int g_count;

__device__ __forceinline__ unsigned h2u(__half2 h) {
    return *reinterpret_cast<unsigned*>(&h);
}
__device__ __forceinline__ ull pkrec(__half2 ab, __half2 cd) {
    ull r;
    asm("mov.b64 %0, {%1, %2};" : "=l"(r) : "r"(h2u(ab)), "r"(h2u(cd)));
    return r;
}

__global__ __launch_bounds__(512, 3)
void ssim_tile_kernel(const float* __restrict__ pred,
                      const float* __restrict__ targ,
                      float* __restrict__ out)
{
    extern __shared__ char smem[];
    __half2 (*sX)[XP] = (__half2(*)[XP])(smem + SX_OFF);
    HQrec   (*hQ)[HP] = (HQrec(*)[HP])(smem + HQ_OFF);
    float* red    = (float*)(smem + RED_OFF);
    int* lastflag = (int*)(smem + RED_OFF + 16*4);

    const int tid = threadIdx.x;
    const int ty0 = blockIdx.y * TH;
    const int tx0 = blockIdx.x * TW;
    const size_t pbase = (size_t)blockIdx.z * (IMG_H * IMG_W);

    // ---- load halo tile, compute centered (u', v), store half2 ----
    const bool interior = (blockIdx.x != 0) & (blockIdx.x != GX - 1) &
                          (blockIdx.y != 0) & (blockIdx.y != GY - 1);
    if (interior) {
        #pragma unroll
        for (int it = 0; it < 12; it++) {
            int idx = tid + it * 512;
            if (idx < EH * EW) {
                int r = idx / EW;
                int c = idx - r * EW;
                size_t off = pbase + (size_t)(ty0 + r - HALO) * IMG_W
                           + (tx0 + c - HALO);
                float a = pred[off];
                float b = targ[off];
                sX[r][c] = __floats2half2_rn(a + b - 1.0f, a - b);
            }
        }
    } else {
        #pragma unroll
        for (int it = 0; it < 12; it++) {
            int idx = tid + it * 512;
            if (idx < EH * EW) {
                int r = idx / EW;
                int c = idx - r * EW;
                int gy = ty0 + r - HALO;
                int gx = tx0 + c - HALO;
                bool ok = ((unsigned)gy < (unsigned)IMG_H) &
                          ((unsigned)gx < (unsigned)IMG_W);
                float a = 0.f, b = 0.f;
                if (ok) {
                    size_t off = pbase + (size_t)gy * IMG_W + gx;
                    a = pred[off];
                    b = targ[off];
                }
                sX[r][c] = __floats2half2_rn(a + b - 1.0f, a - b);
            }
        }
    }
    __syncthreads();

    // ---- horizontal pass: 138 rows x 8 quad-groups = 1104 items ----
    #pragma unroll
    for (int it = 0; it < 3; it++) {
        int g = tid + it * 512;
        if (it < 2 || g < EH * (TW / 4)) {   // it<2 statically full
            const int r  = g >> 3;
            const int c0 = (g & 7) * 4;
            __half2 aX[4], aY[4];
            #pragma unroll
            for (int j = 0; j < 4; j++) {
                aX[j] = __floats2half2_rn(0.f, 0.f);
                aY[j] = aX[j];
            }

            // 14 taps as 7 aligned 8B pair-loads (r*XP + c0 is even)
            const ull* rowp = (const ull*)(&sX[r][c0]);
            #pragma unroll
            for (int ip = 0; ip < 7; ip++) {
                ull pr = rowp[ip];
                __half2 X0 = ((const __half2*)&pr)[0];
                __half2 X1 = ((const __half2*)&pr)[1];
                __half2 Y0 = __hmul2(X0, X0);
                __half2 Y1 = __hmul2(X1, X1);
                #pragma unroll
                for (int j = 0; j < 4; j++) {
                    int k0 = 2 * ip - j;
                    if (k0 >= 0 && k0 <= 10) {
                        __half2 w2 = __float2half2_rn(GW[k0]);
                        aX[j] = __hfma2(X0, w2, aX[j]);
                        aY[j] = __hfma2(Y0, w2, aY[j]);
                    }
                    int k1 = 2 * ip + 1 - j;
                    if (k1 >= 0 && k1 <= 10) {
                        __half2 w2 = __float2half2_rn(GW[k1]);
                        aX[j] = __hfma2(X1, w2, aX[j]);
                        aY[j] = __hfma2(Y1, w2, aY[j]);
                    }
                }
            }
            // store 4 records as 2x STS.128 (16B-aligned: r*HP + c0 even)
            ulonglong2 v01, v23;
            v01.x = pkrec(aX[0], aY[0]);
            v01.y = pkrec(aX[1], aY[1]);
            v23.x = pkrec(aX[2], aY[2]);
            v23.y = pkrec(aX[3], aY[3]);
            ulonglong2* dst = (ulonglong2*)(&hQ[r][c0]);
            dst[0] = v01;
            dst[1] = v23;
        }
    }
    __syncthreads();

    // ---- vertical pass + SSIM: thread -> (x, 8 rows as 2 rounds of 4) ----
    const int x   = tid & 31;
    const int yb  = (tid >> 5) * 8;    // 0..120

    float lsum = 0.f;
    const float C1 = 1e-4f;
    const float C2 = 9e-4f;

    #pragma unroll 1
    for (int rd = 0; rd < 2; rd++) {
        const int y0 = yb + rd * 4;

        __half2 vX[4], vY[4];
        #pragma unroll
        for (int j = 0; j < 4; j++) {
            vX[j] = __floats2half2_rn(0.f, 0.f);
            vY[j] = vX[j];
        }

        #pragma unroll
        for (int i = 0; i < 14; i++) {
            HQrec q = hQ[y0 + i][x];   // one LDS.64 per tap
            #pragma unroll
            for (int j = 0; j < 4; j++) {
                int k = i - j;
                if (k >= 0 && k <= 10) {
                    __half2 w2 = __float2half2_rn(GW[k]);
                    vX[j] = __hfma2(q.ab, w2, vX[j]);
                    vY[j] = __hfma2(q.cd, w2, vY[j]);
                }
            }
        }

        #pragma unroll
        for (int j = 0; j < 4; j++) {
            float Ap = __low2float(vX[j]);    // A' = A - 1
            float B  = __high2float(vX[j]);
            float Cp = __low2float(vY[j]);    // C' = C - 2A' - 1
            float Dv = __high2float(vY[j]);
            float A2 = fmaf(Ap, Ap + 2.0f, 1.0f);   // A^2
            float B2 = B * B;
            float t2m12 = (A2 - B2) * 0.5f;
            float msum  = (A2 + B2) * 0.5f;
            float e = Ap + 0.5f;                    // (C-D)/2 recovery term
            float t2s12 = (Cp - Dv) * 0.5f + e - t2m12;
            float ssum  = (Cp + Dv) * 0.5f + e - msum;
            float num = (t2m12 + C1) * (t2s12 + C2);
            float den = (msum + C1) * (ssum + C2) + 1e-8f;
            lsum += __fdividef(num, den);
        }
    }

    // ---- block reduce, unique partial slot ----
    #pragma unroll
    for (int o = 16; o; o >>= 1)
        lsum += __shfl_xor_sync(0xffffffffu, lsum, o);
    if ((tid & 31) == 0) red[tid >> 5] = lsum;
    __syncthreads();

    if (tid == 0) {
        float s = 0.f;
        #pragma unroll
        for (int w = 0; w < 16; w++) s += red[w];
        int bid = (blockIdx.z * GY + blockIdx.y) * GX + blockIdx.x;
        g_part[bid] = s;
        __threadfence();
        unsigned int prev = atomicAdd(&g_count, 1u);
        *lastflag = (prev == NBLK - 1) ? 1 : 0;
    }
    __syncthreads();

    // ---- last block: final reduction over all partials ----
    if (*lastflag) {
        __threadfence();
        const float4* p4 = (const float4*)g_part;
        float s = 0.f;
        #pragma unroll
        for (int it = 0; it < 3; it++) {
            float4 v = p4[tid + it * 512];
            s += (v.x + v.y) + (v.z + v.w);
        }
        #pragma unroll
        for (int o = 16; o; o >>= 1)
            s += __shfl_xor_sync(0xffffffffu, s, o);
        if ((tid & 31) == 0) red[tid >> 5] = s;
        __syncthreads();
        if (tid == 0) {
            float t = 0.f;
            #pragma unroll
            for (int w = 0; w < 16; w++) t += red[w];
            out[0] = (float)(1.0 - (double)t * (1.0 / N_PIX));
            g_count = 0;   // self-reset for next graph replay
        }
    }
}

extern "C" void kernel_launch(void* const* d_in, const int* in_sizes, int n_in,
                              void* d_out, int out_size)
{
    const float* pred = (const float*)d_in[0];
    const float* targ = (const float*)d_in[1];

    cudaFuncSetAttribute(ssim_tile_kernel,
                         cudaFuncAttributeMaxDynamicSharedMemorySize, SMEM_TOTAL);
    dim3 grid(GX, GY, N_PLANES);   // 16 x 4 x 96
    ssim_tile_kernel<<<grid, 512, SMEM_TOTAL>>>(pred, targ, (float*)d_out);
}

// round 17
// speedup vs baseline: 1.5635x; 1.0200x over previous
#include <cuda_runtime.h>
#include <cuda_fp16.h>

// SSIM loss, single fused kernel, fp16 datapath with CENTERED fields.
// u' = p+t-1, v = p-t. Conv fields X=(u',v), Y=(u'^2,v^2) as half2.
// R17 = R16 (127.5us) + compressed epilogue: ratio scaled by 4 and
// identities E-M = B^2-A'^2, E-S = -(A'^2+B^2) with E=2A'+1:
//   H=B2-G, K=B2+G, M=E-H, S=E+K, T=(C'-D)+H, U=(C'+D)-K
//   ssim = (M+2C1)(T+2C2) / ((S+2C1)(U+2C2)+4e-8)
// 18 fma-pipe ops/px vs 21 (same 4 independent chains, shorter depth).
// Layouts: XP=42 (2-way banked h-pass pair loads), HP=34 (STS.128 stores).

#define TW    32
#define TH    128
#define HALO  5
#define EW    42
#define EH    138
#define XP    42              // pitch (half2): stride 168B -> 2-way conflicts
#define HP    34              // pitch (8B rec), EVEN -> 16B-aligned pair STS

#define IMG_H 512
#define IMG_W 512
#define N_PLANES 96
#define GX    16
#define GY    4
#define NBLK  (GX*GY*N_PLANES)   // 6144
#define N_PIX 25165824.0

#define SX_OFF   0
#define HQ_OFF   (EH*XP*4)             // 23184
#define RED_OFF  (HQ_OFF + EH*HP*8)    // 60720
#define SMEM_TOTAL (RED_OFF + 16*4 + 16)   // ~59.4KB -> 3 blocks/SM

typedef unsigned long long ull;

__device__ constexpr float GW[11] = {
    0.00102838f, 0.00759877f, 0.03600077f, 0.10936071f, 0.21300553f,
    0.26601175f,
    0.21300553f, 0.10936071f, 0.03600077f, 0.00759877f, 0.00102838f
};

struct __align__(8) HQrec { __half2 ab; __half2 cd; };

__device__ float g_part[NBLK];
__device__ unsigned int g_count;

__device__ __forceinline__ unsigned h2u(__half2 h) {
    return *reinterpret_cast<unsigned*>(&h);
}
__device__ __forceinline__ ull pkrec(__half2 ab, __half2 cd) {
    ull r;
    asm("mov.b64 %0, {%1, %2};" : "=l"(r) : "r"(h2u(ab)), "r"(h2u(cd)));
    return r;
}

__global__ __launch_bounds__(512, 3)
void ssim_tile_kernel(const float* __restrict__ pred,
                      const float* __restrict__ targ,
                      float* __restrict__ out)
{
    extern __shared__ char smem[];
    __half2 (*sX)[XP] = (__half2(*)[XP])(smem + SX_OFF);
    HQrec   (*hQ)[HP] = (HQrec(*)[HP])(smem + HQ_OFF);
    float* red    = (float*)(smem + RED_OFF);
    int* lastflag = (int*)(smem + RED_OFF + 16*4);

    const int tid = threadIdx.x;
    const int ty0 = blockIdx.y * TH;
    const int tx0 = blockIdx.x * TW;
    const size_t pbase = (size_t)blockIdx.z * (IMG_H * IMG_W);

    // ---- load halo tile, compute centered (u', v), store half2 ----
    const bool interior = (blockIdx.x != 0) & (blockIdx.x != GX - 1) &
                          (blockIdx.y != 0) & (blockIdx.y != GY - 1);
    if (interior) {
        #pragma unroll
        for (int it = 0; it < 12; it++) {
            int idx = tid + it * 512;
            if (idx < EH * EW) {
                int r = idx / EW;
                int c = idx - r * EW;
                size_t off = pbase + (size_t)(ty0 + r - HALO) * IMG_W
                           + (tx0 + c - HALO);
                float a = pred[off];
                float b = targ[off];
                sX[r][c] = __floats2half2_rn(a + b - 1.0f, a - b);
            }
        }
    } else {
        #pragma unroll
        for (int it = 0; it < 12; it++) {
            int idx = tid + it * 512;
            if (idx < EH * EW) {
                int r = idx / EW;
                int c = idx - r * EW;
                int gy = ty0 + r - HALO;
                int gx = tx0 + c - HALO;
                bool ok = ((unsigned)gy < (unsigned)IMG_H) &
                          ((unsigned)gx < (unsigned)IMG_W);
                float a = 0.f, b = 0.f;
                if (ok) {
                    size_t off = pbase + (size_t)gy * IMG_W + gx;
                    a = pred[off];
                    b = targ[off];
                }
                sX[r][c] = __floats2half2_rn(a + b - 1.0f, a - b);
            }
        }
    }
    __syncthreads();

    // ---- horizontal pass: 138 rows x 8 quad-groups = 1104 items ----
    #pragma unroll
    for (int it = 0; it < 3; it++) {
        int g = tid + it * 512;
        if (it < 2 || g < EH * (TW / 4)) {   // it<2 statically full
            const int r  = g >> 3;
            const int c0 = (g & 7) * 4;
            __half2 aX[4], aY[4];
            #pragma unroll
            for (int j = 0; j < 4; j++) {
                aX[j] = __floats2half2_rn(0.f, 0.f);
                aY[j] = aX[j];
            }

            // 14 taps as 7 aligned 8B pair-loads (r*XP + c0 is even)
            const ull* rowp = (const ull*)(&sX[r][c0]);
            #pragma unroll
            for (int ip = 0; ip < 7; ip++) {
                ull pr = rowp[ip];
                __half2 X0 = ((const __half2*)&pr)[0];
                __half2 X1 = ((const __half2*)&pr)[1];
                __half2 Y0 = __hmul2(X0, X0);
                __half2 Y1 = __hmul2(X1, X1);
                #pragma unroll
                for (int j = 0; j < 4; j++) {
                    int k0 = 2 * ip - j;
                    if (k0 >= 0 && k0 <= 10) {
                        __half2 w2 = __float2half2_rn(GW[k0]);
                        aX[j] = __hfma2(X0, w2, aX[j]);
                        aY[j] = __hfma2(Y0, w2, aY[j]);
                    }
                    int k1 = 2 * ip + 1 - j;
                    if (k1 >= 0 && k1 <= 10) {
                        __half2 w2 = __float2half2_rn(GW[k1]);
                        aX[j] = __hfma2(X1, w2, aX[j]);
                        aY[j] = __hfma2(Y1, w2, aY[j]);
                    }
                }
            }
            // store 4 records as 2x STS.128 (16B-aligned: r*HP + c0 even)
            ulonglong2 v01, v23;
            v01.x = pkrec(aX[0], aY[0]);
            v01.y = pkrec(aX[1], aY[1]);
            v23.x = pkrec(aX[2], aY[2]);
            v23.y = pkrec(aX[3], aY[3]);
            ulonglong2* dst = (ulonglong2*)(&hQ[r][c0]);
            dst[0] = v01;
            dst[1] = v23;
        }
    }
    __syncthreads();

    // ---- vertical pass + SSIM: thread -> (x, 8 rows as 2 rounds of 4) ----
    const int x   = tid & 31;
    const int yb  = (tid >> 5) * 8;    // 0..120

    float lsum = 0.f;
    const float C1x2 = 2e-4f;          // 2*C1
    const float C2x2 = 1.8e-3f;        // 2*C2
    const float EPS4 = 4e-8f;          // 4*1e-8

    #pragma unroll 1
    for (int rd = 0; rd < 2; rd++) {
        const int y0 = yb + rd * 4;

        __half2 vX[4], vY[4];
        #pragma unroll
        for (int j = 0; j < 4; j++) {
            vX[j] = __floats2half2_rn(0.f, 0.f);
            vY[j] = vX[j];
        }

        #pragma unroll
        for (int i = 0; i < 14; i++) {
            HQrec q = hQ[y0 + i][x];   // one LDS.64 per tap
            #pragma unroll
            for (int j = 0; j < 4; j++) {
                int k = i - j;
                if (k >= 0 && k <= 10) {
                    __half2 w2 = __float2half2_rn(GW[k]);
                    vX[j] = __hfma2(q.ab, w2, vX[j]);
                    vY[j] = __hfma2(q.cd, w2, vY[j]);
                }
            }
        }

        // compressed epilogue: ratio scaled by 4 (invariant)
        #pragma unroll
        for (int j = 0; j < 4; j++) {
            float Ap = __low2float(vX[j]);    // A' = A - 1
            float B  = __high2float(vX[j]);
            float Cp = __low2float(vY[j]);    // C' = C - 2A' - 1
            float Dv = __high2float(vY[j]);
            float G  = Ap * Ap;
            float B2 = B * B;
            float H  = B2 - G;                // E - M
            float K  = B2 + G;                // S - E
            float E  = fmaf(Ap, 2.0f, 1.0f);  // 2A'+1
            float M  = E - H;                 // A^2 - B^2  (= 4*m12 / 2... 2x t2m12)
            float S  = E + K;                 // A^2 + B^2
            float T  = (Cp - Dv) + H;         // 4*s12 + M - M = 2x t2s12
            float U  = (Cp + Dv) - K;         // 2x ssum
            float num = (M + C1x2) * (T + C2x2);
            float den = fmaf(S + C1x2, U + C2x2, EPS4);
            lsum += __fdividef(num, den);
        }
    }

    // ---- block reduce, unique partial slot ----
    #pragma unroll
    for (int o = 16; o; o >>= 1)
        lsum += __shfl_xor_sync(0xffffffffu, lsum, o);
    if ((tid & 31) == 0) red[tid >> 5] = lsum;
    __syncthreads();

    if (tid == 0) {
        float s = 0.f;
        #pragma unroll
        for (int w = 0; w < 16; w++) s += red[w];
        int bid = (blockIdx.z * GY + blockIdx.y) * GX + blockIdx.x;
        g_part[bid] = s;
        __threadfence();
        unsigned int prev = atomicAdd(&g_count, 1u);
        *lastflag = (prev == NBLK - 1) ? 1 : 0;
    }
    __syncthreads();

    // ---- last block: final reduction over all partials ----
    if (*lastflag) {
        __threadfence();
        const float4* p4 = (const float4*)g_part;
        float s = 0.f;
        #pragma unroll
        for (int it = 0; it < 3; it++) {
            float4 v = p4[tid + it * 512];
            s += (v.x + v.y) + (v.z + v.w);
        }
        #pragma unroll
        for (int o = 16; o; o >>= 1)
            s += __shfl_xor_sync(0xffffffffu, s, o);
        if ((tid & 31) == 0) red[tid >> 5] = s;
        __syncthreads();
        if (tid == 0) {
            float t = 0.f;
            #pragma unroll
            for (int w = 0; w < 16; w++) t += red[w];
            out[0] = (float)(1.0 - (double)t * (1.0 / N_PIX));
            g_count = 0;   // self-reset for next graph replay
        }
    }
}

extern "C" void kernel_launch(void* const* d_in, const int* in_sizes, int n_in,
                              void* d_out, int out_size)
{
    const float* pred = (const float*)d_in[0];
    const float* targ = (const float*)d_in[1];

    cudaFuncSetAttribute(ssim_tile_kernel,
                         cudaFuncAttributeMaxDynamicSharedMemorySize, SMEM_TOTAL);
    dim3 grid(GX, GY, N_PLANES);   // 16 x 4 x 96
    ssim_tile_kernel<<<grid, 512, SMEM_TOTAL>>>(pred, targ, (float*)d_out);
}